// round 14
// baseline (speedup 1.0000x reference)
#include <cuda_runtime.h>
#include <cuda_bf16.h>
#include <math.h>
#include <stdint.h>

// ---------------- problem constants ----------------
#define Bc   2
#define Sc   2048
#define Hc   1024
#define NHc  16
#define HDc  64
#define MLPc 32
#define Mtot (Bc*Sc)   // 4096

// ---------------- scratch ----------------
__device__ __nv_bfloat16 g_hsb[(size_t)Mtot*Hc];
__device__ __nv_bfloat16 g_WT[(size_t)4*Hc*Hc];
__device__ __nv_bfloat16 g_Qb[(size_t)Bc*NHc*Sc*HDc];
__device__ __nv_bfloat16 g_Kb[(size_t)Bc*NHc*Sc*HDc];
__device__ __nv_bfloat16 g_Vb[(size_t)Bc*NHc*Sc*HDc];   // (B,NH,S,HD) like K
__device__ __nv_bfloat16 g_attnb[(size_t)Mtot*Hc];
__device__ float g_reach[Bc*NHc*Sc];
__device__ float g_attract[Bc*NHc*Sc];
__device__ float g_proj[(size_t)Mtot*Hc];

// ---------------- helpers ----------------
__device__ __forceinline__ void mma16(float* c,
    unsigned a0, unsigned a1, unsigned a2, unsigned a3,
    unsigned b0, unsigned b1)
{
    asm volatile(
      "mma.sync.aligned.m16n8k16.row.col.f32.bf16.bf16.f32 "
      "{%0,%1,%2,%3}, {%4,%5,%6,%7}, {%8,%9}, {%0,%1,%2,%3};"
      : "+f"(c[0]), "+f"(c[1]), "+f"(c[2]), "+f"(c[3])
      : "r"(a0), "r"(a1), "r"(a2), "r"(a3), "r"(b0), "r"(b1));
}
__device__ __forceinline__ void ldsm4(unsigned* d, uint32_t addr){
    asm volatile("ldmatrix.sync.aligned.m8n8.x4.shared.b16 {%0,%1,%2,%3}, [%4];"
      : "=r"(d[0]), "=r"(d[1]), "=r"(d[2]), "=r"(d[3]) : "r"(addr));
}
__device__ __forceinline__ void ldsm4t(unsigned* d, uint32_t addr){
    asm volatile("ldmatrix.sync.aligned.m8n8.x4.trans.shared.b16 {%0,%1,%2,%3}, [%4];"
      : "=r"(d[0]), "=r"(d[1]), "=r"(d[2]), "=r"(d[3]) : "r"(addr));
}
__device__ __forceinline__ void cpa16(uint32_t s, const void* g){
    asm volatile("cp.async.cg.shared.global [%0], [%1], 16;\n" :: "r"(s), "l"(g));
}
#define CP_COMMIT()  asm volatile("cp.async.commit_group;\n" ::: "memory")
#define CP_WAIT(N)   asm volatile("cp.async.wait_group %0;\n" :: "n"(N) : "memory")

__device__ __forceinline__ uint32_t smem_u32(const void* p){
    uint32_t a;
    asm("{ .reg .u64 t; cvta.to.shared.u64 t, %1; cvt.u32.u64 %0, t; }" : "=r"(a) : "l"(p));
    return a;
}
__device__ __forceinline__ unsigned packbf(float lo, float hi){
    __nv_bfloat162 t = __float22bfloat162_rn(make_float2(lo, hi));
    return *reinterpret_cast<unsigned*>(&t);
}
__device__ __forceinline__ float ex2(float x){
    float r; asm("ex2.approx.f32 %0, %1;" : "=f"(r) : "f"(x)); return r;
}
__device__ __forceinline__ float tanhA(float x){
    float r; asm("tanh.approx.f32 %0, %1;" : "=f"(r) : "f"(x)); return r;
}

// ---------------- fp32 -> bf16 conversion of hidden states ----------------
__global__ void cvt_hs(const float* __restrict__ hs){
    int i = blockIdx.x * blockDim.x + threadIdx.x;
    const float4* p = (const float4*)hs;
    float4 v0 = p[2*i], v1 = p[2*i+1];
    unsigned u[4] = { packbf(v0.x,v0.y), packbf(v0.z,v0.w),
                      packbf(v1.x,v1.y), packbf(v1.z,v1.w) };
    *(uint4*)&g_hsb[(size_t)8*i] = *(uint4*)u;
}

// ---------------- weight transpose to bf16 ----------------
__global__ void transpose_w(const float* __restrict__ W0, const float* __restrict__ W1,
                            const float* __restrict__ W2, const float* __restrict__ W3)
{
    __shared__ float t[32][33];
    int mat = blockIdx.z;
    const float* W = (mat==0)?W0:(mat==1)?W1:(mat==2)?W2:W3;
    __nv_bfloat16* WT = g_WT + (size_t)mat*Hc*Hc;
    int kb = blockIdx.x*32, nb = blockIdx.y*32;
    int tx = threadIdx.x, ty = threadIdx.y;
    #pragma unroll
    for (int i = 0; i < 32; i += 8)
        t[ty+i][tx] = W[(size_t)(kb+ty+i)*Hc + nb+tx];
    __syncthreads();
    #pragma unroll
    for (int i = 0; i < 32; i += 8)
        WT[(size_t)(nb+ty+i)*Hc + kb+tx] = __float2bfloat16(t[tx][ty+i]);
}

// ---------------- mask MLPs ----------------
__global__ void mask_mlp_kernel(const float* __restrict__ imp,
    const float* __restrict__ rw1, const float* __restrict__ rb1,
    const float* __restrict__ rw2, const float* __restrict__ rb2,
    const float* __restrict__ aw1, const float* __restrict__ ab1,
    const float* __restrict__ aw2, const float* __restrict__ ab2)
{
    int idx = blockIdx.x * blockDim.x + threadIdx.x;
    if (idx >= Bc*Sc) return;
    float x = imp[idx];
    float hr[MLPc], ha[MLPc];
    const float kInvSqrt2 = 0.70710678118654752440f;
    #pragma unroll
    for (int j = 0; j < MLPc; j++) {
        float t = fmaf(x, rw1[j], rb1[j]);
        hr[j] = 0.5f * t * (1.0f + erff(t * kInvSqrt2));
        float u = fmaf(x, aw1[j], ab1[j]);
        ha[j] = 0.5f * u * (1.0f + erff(u * kInvSqrt2));
    }
    int b = idx / Sc, s = idx - b * Sc;
    #pragma unroll
    for (int h = 0; h < NHc; h++) {
        float rs = rb2[h], as = ab2[h];
        #pragma unroll
        for (int j = 0; j < MLPc; j++) {
            rs = fmaf(hr[j], rw2[j*NHc + h], rs);
            as = fmaf(ha[j], aw2[j*NHc + h], as);
        }
        g_reach[(b*NHc + h)*Sc + s]   = rs;
        g_attract[(b*NHc + h)*Sc + s] = as;
    }
}

// ---------------- bf16 tensor-core GEMM: K-chunk 32, 4 stages ----------------
#define AST2 40
#define ASZ2 (128*AST2)
#define STG2 (2*ASZ2)
#define G_SMEMB (4*STG2*2)

template<int MODE>
__global__ __launch_bounds__(256, 2) void gemm_tc(
    const float* __restrict__ b0p, const float* __restrict__ b1p,
    const float* __restrict__ b2p)
{
    extern __shared__ __nv_bfloat16 smB[];
    uint32_t smb = smem_u32(smB);

    const __nv_bfloat16* A = (MODE == 1) ? g_attnb : g_hsb;
    int wsel = (MODE == 0) ? (blockIdx.x >> 3) : 3;
    const __nv_bfloat16* WT = g_WT + (size_t)wsel * Hc * Hc;
    const float* bias = (MODE == 1) ? b0p : ((wsel == 0) ? b0p : (wsel == 1) ? b1p : b2p);
    int n0 = (MODE == 0) ? ((blockIdx.x & 7) * 128) : (blockIdx.x * 128);
    int m0 = blockIdx.y * 128;

    int tid = threadIdx.x;
    int wid = tid >> 5, lane = tid & 31;
    int mw = wid & 3, nw = wid >> 2;
    int g = lane >> 2, tq = lane & 3;

    int crow = tid >> 2, ccol = (tid & 3) * 8;

    float C[2][8][4];
    #pragma unroll
    for (int mt = 0; mt < 2; mt++)
        #pragma unroll
        for (int nt = 0; nt < 8; nt++)
            #pragma unroll
            for (int q = 0; q < 4; q++) C[mt][nt][q] = 0.f;

    #pragma unroll
    for (int s = 0; s < 3; s++) {
        int k0 = s * 32;
        uint32_t base = smb + (uint32_t)(s * STG2) * 2u;
        cpa16(base + (crow*AST2 + ccol)*2,        &A[(size_t)(m0 + crow)*Hc + k0 + ccol]);
        cpa16(base + ((crow+64)*AST2 + ccol)*2,   &A[(size_t)(m0 + crow + 64)*Hc + k0 + ccol]);
        cpa16(base + (ASZ2 + crow*AST2 + ccol)*2, &WT[(size_t)(n0 + crow)*Hc + k0 + ccol]);
        cpa16(base + (ASZ2 + (crow+64)*AST2 + ccol)*2, &WT[(size_t)(n0 + crow + 64)*Hc + k0 + ccol]);
        CP_COMMIT();
    }

    int l15 = lane & 15;
    int lc8 = (lane & 16) >> 1;
    uint32_t a_ld = smb + (uint32_t)(((mw*32 + l15)*AST2 + lc8) * 2);
    uint32_t b_ld = smb + (uint32_t)ASZ2*2u + (uint32_t)(((nw*64 + l15)*AST2 + lc8) * 2);

    for (int kt = 0; kt < 32; kt++) {
        CP_WAIT(2);
        __syncthreads();
        if (kt + 3 < 32) {
            int k0 = (kt + 3) * 32;
            uint32_t base = smb + (uint32_t)(((kt + 3) & 3) * STG2) * 2u;
            cpa16(base + (crow*AST2 + ccol)*2,        &A[(size_t)(m0 + crow)*Hc + k0 + ccol]);
            cpa16(base + ((crow+64)*AST2 + ccol)*2,   &A[(size_t)(m0 + crow + 64)*Hc + k0 + ccol]);
            cpa16(base + (ASZ2 + crow*AST2 + ccol)*2, &WT[(size_t)(n0 + crow)*Hc + k0 + ccol]);
            cpa16(base + (ASZ2 + (crow+64)*AST2 + ccol)*2, &WT[(size_t)(n0 + crow + 64)*Hc + k0 + ccol]);
        }
        CP_COMMIT();

        uint32_t so = (uint32_t)((kt & 3) * STG2) * 2u;
        #pragma unroll
        for (int ks = 0; ks < 2; ks++) {
            unsigned a0f[4], a1f[4];
            ldsm4(a0f, a_ld + so + ks*32);
            ldsm4(a1f, a_ld + so + (uint32_t)(16*AST2)*2u + ks*32);
            #pragma unroll
            for (int ntp = 0; ntp < 4; ntp++) {
                unsigned bb[4];
                ldsm4(bb, b_ld + so + (uint32_t)(ntp*16*AST2)*2u + ks*32);
                mma16(C[0][2*ntp],   a0f[0],a0f[1],a0f[2],a0f[3], bb[0], bb[2]);
                mma16(C[1][2*ntp],   a1f[0],a1f[1],a1f[2],a1f[3], bb[0], bb[2]);
                mma16(C[0][2*ntp+1], a0f[0],a0f[1],a0f[2],a0f[3], bb[1], bb[3]);
                mma16(C[1][2*ntp+1], a1f[0],a1f[1],a1f[2],a1f[3], bb[1], bb[3]);
            }
        }
    }

    #pragma unroll
    for (int mt = 0; mt < 2; mt++) {
        int r0 = m0 + mw*32 + mt*16 + g;
        #pragma unroll
        for (int nt = 0; nt < 8; nt++) {
            int col = n0 + nw*64 + nt*8 + 2*tq;
            float2 bv = *(const float2*)&bias[col];
            float c00 = C[mt][nt][0] + bv.x, c01 = C[mt][nt][1] + bv.y;
            float c10 = C[mt][nt][2] + bv.x, c11 = C[mt][nt][3] + bv.y;
            if (MODE == 0) {
                int hh = col >> 6, dd = col & 63;
                int bb2 = r0 >> 11, ss0 = r0 & 2047;
                __nv_bfloat16* outp = (wsel == 0) ? g_Qb : (wsel == 1) ? g_Kb : g_Vb;
                size_t i0 = (((size_t)bb2*NHc + hh)*Sc + ss0)*HDc + dd;
                *(unsigned*)&outp[i0]          = packbf(c00, c01);
                *(unsigned*)&outp[i0 + 8*HDc]  = packbf(c10, c11);
            } else {
                *(float2*)&g_proj[(size_t)r0*Hc + col]     = make_float2(c00, c01);
                *(float2*)&g_proj[(size_t)(r0+8)*Hc + col] = make_float2(c10, c11);
            }
        }
    }
}

// ---------------- bf16 flash attention: 128q x 64k, 3-stage, 3 CTAs/SM ------
// V stored (B,NH,S,HD); PV B-fragments via ldmatrix.trans.
#define FSTB 72
#define FQ_BYTES (128*FSTB*2)
#define FK_BYTES (64*FSTB*2)
#define FSTG_BYTES (2*FK_BYTES + 256)
#define FL_SMEMB (FQ_BYTES + 3*FSTG_BYTES)   // 74496 B; 3 CTAs = 223.5KB <= 228KB

__global__ __launch_bounds__(128, 3) void flash_tc(const float* __restrict__ log_temp)
{
    extern __shared__ char smc[];
    uint32_t smb = smem_u32(smc);
    int tid = threadIdx.x, wid = tid >> 5, lane = tid & 31;
    int g = lane >> 2, tq = lane & 3;
    int bh = blockIdx.y, b = bh >> 4, h = bh & 15;
    int q0 = blockIdx.x * 128;

    const __nv_bfloat16* Qg = g_Qb + ((size_t)bh*Sc + q0) * HDc;
    const __nv_bfloat16* Kg = g_Kb + (size_t)bh*Sc*HDc;
    const __nv_bfloat16* Vg = g_Vb + (size_t)bh*Sc*HDc;
    const float* att = g_attract + bh*Sc;

    #pragma unroll
    for (int l = 0; l < 8; l++) {
        int idx = tid + 128*l; int r = idx >> 3, c = (idx & 7) * 8;
        cpa16(smb + (uint32_t)((r*FSTB + c)*2), &Qg[r*HDc + c]);
    }
    #pragma unroll
    for (int s = 0; s < 2; s++) {
        uint32_t base = smb + (uint32_t)(FQ_BYTES + s*FSTG_BYTES);
        int kn = s * 64;
        #pragma unroll
        for (int l = 0; l < 4; l++) {
            int idx = tid + 128*l; int r = idx >> 3, c = (idx & 7) * 8;
            cpa16(base + (uint32_t)((r*FSTB + c)*2), &Kg[(size_t)(kn + r)*HDc + c]);
            cpa16(base + (uint32_t)FK_BYTES + (uint32_t)((r*FSTB + c)*2), &Vg[(size_t)(kn + r)*HDc + c]);
        }
        if (tid < 16) cpa16(base + (uint32_t)(2*FK_BYTES) + tid*16, &att[kn + tid*4]);
        CP_COMMIT();
    }

    int l15 = lane & 15;
    int lc8 = (lane & 16) >> 1;
    uint32_t qa   = smb + (uint32_t)(((wid*32 + l15)*FSTB + lc8) * 2);
    uint32_t kvof = (uint32_t)((l15*FSTB + lc8) * 2);
    uint32_t vof = (uint32_t)((((lane & 7) + ((lane & 16) >> 1))*FSTB + (lane & 8)) * 2);

    const float L2E = 1.44269504088896f;
    const float SCL = 0.125f * L2E;

    float reach05[2][2], ip[2][2];
    #pragma unroll
    for (int mt = 0; mt < 2; mt++) {
        int rr = q0 + wid*32 + mt*16 + g;
        reach05[mt][0] = 0.5f * g_reach[bh*Sc + rr];
        reach05[mt][1] = 0.5f * g_reach[bh*Sc + rr + 8];
        ip[mt][0] = (float)rr; ip[mt][1] = (float)(rr + 8);
    }
    float temp  = __expf(log_temp[h]) + 1.0f;
    float inv05 = __fdividef(0.5f, (float)Sc * temp);
    const float HALF8 = 0.5f + 1e-8f;

    float mrow[2][2], lrow[2][2];
    float O[2][8][4];
    #pragma unroll
    for (int mt = 0; mt < 2; mt++) {
        mrow[mt][0] = mrow[mt][1] = -1e30f;
        lrow[mt][0] = lrow[mt][1] = 0.f;
        #pragma unroll
        for (int nt = 0; nt < 8; nt++)
            #pragma unroll
            for (int q = 0; q < 4; q++) O[mt][nt][q] = 0.f;
    }

    for (int kt = 0; kt < 32; kt++) {
        int k0 = kt * 64;
        CP_WAIT(1);
        __syncthreads();
        if (kt + 2 < 32) {
            int kn = (kt + 2) * 64;
            uint32_t base = smb + (uint32_t)(FQ_BYTES + ((kt + 2) % 3) * FSTG_BYTES);
            #pragma unroll
            for (int l = 0; l < 4; l++) {
                int idx = tid + 128*l; int r = idx >> 3, c = (idx & 7) * 8;
                cpa16(base + (uint32_t)((r*FSTB + c)*2), &Kg[(size_t)(kn + r)*HDc + c]);
                cpa16(base + (uint32_t)FK_BYTES + (uint32_t)((r*FSTB + c)*2), &Vg[(size_t)(kn + r)*HDc + c]);
            }
            if (tid < 16) cpa16(base + (uint32_t)(2*FK_BYTES) + tid*16, &att[kn + tid*4]);
        }
        CP_COMMIT();

        int st = kt % 3;
        uint32_t stg = smb + (uint32_t)(FQ_BYTES + st * FSTG_BYTES);
        uint32_t Kb = stg + kvof;
        uint32_t Vb = stg + (uint32_t)FK_BYTES + vof;
        const float* Att = (const float*)(smc + FQ_BYTES + st * FSTG_BYTES + 2*FK_BYTES);

        // ---- S = Q K^T ----
        float C[2][8][4];
        #pragma unroll
        for (int mt = 0; mt < 2; mt++)
            #pragma unroll
            for (int nt = 0; nt < 8; nt++)
                #pragma unroll
                for (int q = 0; q < 4; q++) C[mt][nt][q] = 0.f;
        #pragma unroll
        for (int ks = 0; ks < 4; ks++) {
            unsigned a0f[4], a1f[4];
            ldsm4(a0f, qa + ks*32);
            ldsm4(a1f, qa + (uint32_t)(16*FSTB)*2u + ks*32);
            #pragma unroll
            for (int ntp = 0; ntp < 4; ntp++) {
                unsigned bb[4];
                ldsm4(bb, Kb + (uint32_t)(ntp*16*FSTB)*2u + ks*32);
                mma16(C[0][2*ntp],   a0f[0],a0f[1],a0f[2],a0f[3], bb[0], bb[2]);
                mma16(C[1][2*ntp],   a1f[0],a1f[1],a1f[2],a1f[3], bb[0], bb[2]);
                mma16(C[0][2*ntp+1], a0f[0],a0f[1],a0f[2],a0f[3], bb[1], bb[3]);
                mma16(C[1][2*ntp+1], a1f[0],a1f[1],a1f[2],a1f[3], bb[1], bb[3]);
            }
        }

        // ---- max pass + corr ----
        float mn[2][2], corr[2][2], mns[2][2];
        #pragma unroll
        for (int mt = 0; mt < 2; mt++) {
            float ml = -1e30f, mh = -1e30f;
            #pragma unroll
            for (int nt = 0; nt < 8; nt++) {
                ml = fmaxf(ml, fmaxf(C[mt][nt][0], C[mt][nt][1]));
                mh = fmaxf(mh, fmaxf(C[mt][nt][2], C[mt][nt][3]));
            }
            ml = fmaxf(ml, __shfl_xor_sync(0xffffffffu, ml, 1));
            ml = fmaxf(ml, __shfl_xor_sync(0xffffffffu, ml, 2));
            mh = fmaxf(mh, __shfl_xor_sync(0xffffffffu, mh, 1));
            mh = fmaxf(mh, __shfl_xor_sync(0xffffffffu, mh, 2));
            mn[mt][0] = fmaxf(mrow[mt][0], ml);
            mn[mt][1] = fmaxf(mrow[mt][1], mh);
            corr[mt][0] = ex2((mrow[mt][0] - mn[mt][0]) * SCL);
            corr[mt][1] = ex2((mrow[mt][1] - mn[mt][1]) * SCL);
            mrow[mt][0] = mn[mt][0]; mrow[mt][1] = mn[mt][1];
            mns[mt][0] = mn[mt][0] * SCL; mns[mt][1] = mn[mt][1] * SCL;
        }

        bool need = (corr[0][0] != 1.f) | (corr[0][1] != 1.f) |
                    (corr[1][0] != 1.f) | (corr[1][1] != 1.f);
        if (__any_sync(0xffffffffu, need)) {
            #pragma unroll
            for (int mt = 0; mt < 2; mt++)
                #pragma unroll
                for (int nt = 0; nt < 8; nt++) {
                    O[mt][nt][0] *= corr[mt][0]; O[mt][nt][1] *= corr[mt][0];
                    O[mt][nt][2] *= corr[mt][1]; O[mt][nt][3] *= corr[mt][1];
                }
        }

        // ---- P = (0.5*tanh(z/2) + 0.5 + 1e-8) * exp2(SCL*C - mns) ----
        #pragma unroll
        for (int mt = 0; mt < 2; mt++) {
            float rs0 = 0.f, rs1 = 0.f;
            #pragma unroll
            for (int nt = 0; nt < 8; nt++) {
                int jc = nt*8 + 2*tq;
                float2 at2 = *(const float2*)&Att[jc];
                float j0 = (float)(k0 + jc), j1 = j0 + 1.0f;
                float a0b = fmaf(at2.x, 0.5f, reach05[mt][0]);
                float a1b = fmaf(at2.y, 0.5f, reach05[mt][0]);
                float b0b = fmaf(at2.x, 0.5f, reach05[mt][1]);
                float b1b = fmaf(at2.y, 0.5f, reach05[mt][1]);
                float zh00 = fmaf(-inv05, fabsf(ip[mt][0] - j0), a0b);
                float zh01 = fmaf(-inv05, fabsf(ip[mt][0] - j1), a1b);
                float zh10 = fmaf(-inv05, fabsf(ip[mt][1] - j0), b0b);
                float zh11 = fmaf(-inv05, fabsf(ip[mt][1] - j1), b1b);
                float w00 = fmaf(tanhA(zh00), 0.5f, HALF8);
                float w01 = fmaf(tanhA(zh01), 0.5f, HALF8);
                float w10 = fmaf(tanhA(zh10), 0.5f, HALF8);
                float w11 = fmaf(tanhA(zh11), 0.5f, HALF8);
                C[mt][nt][0] = w00 * ex2(fmaf(C[mt][nt][0], SCL, -mns[mt][0]));
                C[mt][nt][1] = w01 * ex2(fmaf(C[mt][nt][1], SCL, -mns[mt][0]));
                C[mt][nt][2] = w10 * ex2(fmaf(C[mt][nt][2], SCL, -mns[mt][1]));
                C[mt][nt][3] = w11 * ex2(fmaf(C[mt][nt][3], SCL, -mns[mt][1]));
                rs0 += C[mt][nt][0] + C[mt][nt][1];
                rs1 += C[mt][nt][2] + C[mt][nt][3];
            }
            rs0 += __shfl_xor_sync(0xffffffffu, rs0, 1);
            rs0 += __shfl_xor_sync(0xffffffffu, rs0, 2);
            rs1 += __shfl_xor_sync(0xffffffffu, rs1, 1);
            rs1 += __shfl_xor_sync(0xffffffffu, rs1, 2);
            lrow[mt][0] = fmaf(lrow[mt][0], corr[mt][0], rs0);
            lrow[mt][1] = fmaf(lrow[mt][1], corr[mt][1], rs1);
        }

        // ---- O += P V : trans-ldmatrix V fragments ----
        #pragma unroll
        for (int ks = 0; ks < 4; ks++) {
            unsigned af0[4], af1[4];
            af0[0] = packbf(C[0][2*ks][0],   C[0][2*ks][1]);
            af0[1] = packbf(C[0][2*ks][2],   C[0][2*ks][3]);
            af0[2] = packbf(C[0][2*ks+1][0], C[0][2*ks+1][1]);
            af0[3] = packbf(C[0][2*ks+1][2], C[0][2*ks+1][3]);
            af1[0] = packbf(C[1][2*ks][0],   C[1][2*ks][1]);
            af1[1] = packbf(C[1][2*ks][2],   C[1][2*ks][3]);
            af1[2] = packbf(C[1][2*ks+1][0], C[1][2*ks+1][1]);
            af1[3] = packbf(C[1][2*ks+1][2], C[1][2*ks+1][3]);
            #pragma unroll
            for (int ntp = 0; ntp < 4; ntp++) {
                unsigned bb[4];
                ldsm4t(bb, Vb + (uint32_t)(ks*16*FSTB)*2u + (uint32_t)(ntp*32));
                mma16(O[0][2*ntp],   af0[0],af0[1],af0[2],af0[3], bb[0], bb[2]);
                mma16(O[1][2*ntp],   af1[0],af1[1],af1[2],af1[3], bb[0], bb[2]);
                mma16(O[0][2*ntp+1], af0[0],af0[1],af0[2],af0[3], bb[1], bb[3]);
                mma16(O[1][2*ntp+1], af1[0],af1[1],af1[2],af1[3], bb[1], bb[3]);
            }
        }
    }

    #pragma unroll
    for (int mt = 0; mt < 2; mt++) {
        float il0 = __fdividef(1.f, lrow[mt][0]);
        float il1 = __fdividef(1.f, lrow[mt][1]);
        int rr = q0 + wid*32 + mt*16 + g;
        #pragma unroll
        for (int nt = 0; nt < 8; nt++) {
            int col = h*HDc + nt*8 + 2*tq;
            *(unsigned*)&g_attnb[(size_t)(b*Sc + rr    )*Hc + col] =
                packbf(O[mt][nt][0]*il0, O[mt][nt][1]*il0);
            *(unsigned*)&g_attnb[(size_t)(b*Sc + rr + 8)*Hc + col] =
                packbf(O[mt][nt][2]*il1, O[mt][nt][3]*il1);
        }
    }
}

// ---------------- residual + LayerNorm ----------------
__global__ __launch_bounds__(256) void ln_kernel(
    const float* __restrict__ hs, const float* __restrict__ gamma,
    const float* __restrict__ beta, float* __restrict__ out)
{
    int m = blockIdx.x;
    __shared__ float xs[Hc];
    __shared__ float red[8];
    __shared__ float stat[2];
    int tid = threadIdx.x;
    const float* hrow = hs + (size_t)m*Hc;
    const float* prow = g_proj + (size_t)m*Hc;

    float lsum = 0.f;
    for (int i = tid; i < Hc; i += 256) {
        float x = hrow[i] + prow[i];
        xs[i] = x;
        lsum += x;
    }
    #pragma unroll
    for (int o = 16; o > 0; o >>= 1) lsum += __shfl_xor_sync(0xffffffffu, lsum, o);
    if ((tid & 31) == 0) red[tid >> 5] = lsum;
    __syncthreads();
    if (tid == 0) {
        float s = 0.f;
        #pragma unroll
        for (int i = 0; i < 8; i++) s += red[i];
        stat[0] = s * (1.0f/(float)Hc);
    }
    __syncthreads();
    float mu = stat[0];

    float lvar = 0.f;
    for (int i = tid; i < Hc; i += 256) {
        float d = xs[i] - mu;
        lvar += d*d;
    }
    #pragma unroll
    for (int o = 16; o > 0; o >>= 1) lvar += __shfl_xor_sync(0xffffffffu, lvar, o);
    if ((tid & 31) == 0) red[tid >> 5] = lvar;
    __syncthreads();
    if (tid == 0) {
        float s = 0.f;
        #pragma unroll
        for (int i = 0; i < 8; i++) s += red[i];
        stat[1] = rsqrtf(s * (1.0f/(float)Hc) + 1e-5f);
    }
    __syncthreads();
    float rstd = stat[1];

    float* orow = out + (size_t)m*Hc;
    for (int i = tid; i < Hc; i += 256)
        orow[i] = (xs[i] - mu) * rstd * gamma[i] + beta[i];
}

// ---------------- launch ----------------
extern "C" void kernel_launch(void* const* d_in, const int* in_sizes, int n_in,
                              void* d_out, int out_size) {
    (void)in_sizes; (void)n_in; (void)out_size;
    const float* hs   = (const float*)d_in[0];
    const float* imp  = (const float*)d_in[1];
    const float* wq   = (const float*)d_in[2];
    const float* bq   = (const float*)d_in[3];
    const float* wk   = (const float*)d_in[4];
    const float* bk   = (const float*)d_in[5];
    const float* wv   = (const float*)d_in[6];
    const float* bv   = (const float*)d_in[7];
    const float* wo   = (const float*)d_in[8];
    const float* bo   = (const float*)d_in[9];
    const float* rw1  = (const float*)d_in[10];
    const float* rb1  = (const float*)d_in[11];
    const float* rw2  = (const float*)d_in[12];
    const float* rb2  = (const float*)d_in[13];
    const float* aw1  = (const float*)d_in[14];
    const float* ab1  = (const float*)d_in[15];
    const float* aw2  = (const float*)d_in[16];
    const float* ab2  = (const float*)d_in[17];
    const float* logt = (const float*)d_in[18];
    const float* lng  = (const float*)d_in[19];
    const float* lnb  = (const float*)d_in[20];
    float* out = (float*)d_out;

    cudaFuncSetAttribute(gemm_tc<0>, cudaFuncAttributeMaxDynamicSharedMemorySize, G_SMEMB);
    cudaFuncSetAttribute(gemm_tc<1>, cudaFuncAttributeMaxDynamicSharedMemorySize, G_SMEMB);
    cudaFuncSetAttribute(flash_tc,   cudaFuncAttributeMaxDynamicSharedMemorySize, FL_SMEMB);

    cvt_hs<<<Mtot*Hc/8/256, 256>>>(hs);
    transpose_w<<<dim3(32, 32, 4), dim3(32, 8)>>>(wq, wk, wv, wo);
    mask_mlp_kernel<<<(Bc*Sc + 255)/256, 256>>>(imp, rw1, rb1, rw2, rb2,
                                                aw1, ab1, aw2, ab2);

    gemm_tc<0><<<dim3(24, Mtot/128), 256, G_SMEMB>>>(bq, bk, bv);

    flash_tc<<<dim3(Sc/128, Bc*NHc), 128, FL_SMEMB>>>(logt);

    gemm_tc<1><<<dim3(8, Mtot/128), 256, G_SMEMB>>>(bo, bo, bo);

    ln_kernel<<<Mtot, 256>>>(hs, lng, lnb, out);
}

// round 15
// speedup vs baseline: 1.1315x; 1.1315x over previous
#include <cuda_runtime.h>
#include <cuda_bf16.h>
#include <math.h>
#include <stdint.h>

// ---------------- problem constants ----------------
#define Bc   2
#define Sc   2048
#define Hc   1024
#define NHc  16
#define HDc  64
#define MLPc 32
#define Mtot (Bc*Sc)   // 4096

// ---------------- scratch ----------------
__device__ __nv_bfloat16 g_hsb[(size_t)Mtot*Hc];
__device__ __nv_bfloat16 g_WT[(size_t)4*Hc*Hc];
__device__ __nv_bfloat16 g_Qb[(size_t)Bc*NHc*Sc*HDc];
__device__ __nv_bfloat16 g_Kb[(size_t)Bc*NHc*Sc*HDc];
__device__ __nv_bfloat16 g_Vb[(size_t)Bc*NHc*Sc*HDc];   // (B,NH,S,HD) like K
__device__ __nv_bfloat16 g_attnb[(size_t)Mtot*Hc];
__device__ float g_reach[Bc*NHc*Sc];
__device__ float g_attract[Bc*NHc*Sc];
__device__ float g_proj[(size_t)Mtot*Hc];

// ---------------- helpers ----------------
__device__ __forceinline__ void mma16(float* c,
    unsigned a0, unsigned a1, unsigned a2, unsigned a3,
    unsigned b0, unsigned b1)
{
    asm volatile(
      "mma.sync.aligned.m16n8k16.row.col.f32.bf16.bf16.f32 "
      "{%0,%1,%2,%3}, {%4,%5,%6,%7}, {%8,%9}, {%0,%1,%2,%3};"
      : "+f"(c[0]), "+f"(c[1]), "+f"(c[2]), "+f"(c[3])
      : "r"(a0), "r"(a1), "r"(a2), "r"(a3), "r"(b0), "r"(b1));
}
__device__ __forceinline__ void ldsm4(unsigned* d, uint32_t addr){
    asm volatile("ldmatrix.sync.aligned.m8n8.x4.shared.b16 {%0,%1,%2,%3}, [%4];"
      : "=r"(d[0]), "=r"(d[1]), "=r"(d[2]), "=r"(d[3]) : "r"(addr));
}
__device__ __forceinline__ void ldsm4t(unsigned* d, uint32_t addr){
    asm volatile("ldmatrix.sync.aligned.m8n8.x4.trans.shared.b16 {%0,%1,%2,%3}, [%4];"
      : "=r"(d[0]), "=r"(d[1]), "=r"(d[2]), "=r"(d[3]) : "r"(addr));
}
__device__ __forceinline__ void cpa16(uint32_t s, const void* g){
    asm volatile("cp.async.cg.shared.global [%0], [%1], 16;\n" :: "r"(s), "l"(g));
}
#define CP_COMMIT()  asm volatile("cp.async.commit_group;\n" ::: "memory")
#define CP_WAIT(N)   asm volatile("cp.async.wait_group %0;\n" :: "n"(N) : "memory")

__device__ __forceinline__ uint32_t smem_u32(const void* p){
    uint32_t a;
    asm("{ .reg .u64 t; cvta.to.shared.u64 t, %1; cvt.u32.u64 %0, t; }" : "=r"(a) : "l"(p));
    return a;
}
__device__ __forceinline__ unsigned packbf(float lo, float hi){
    __nv_bfloat162 t = __float22bfloat162_rn(make_float2(lo, hi));
    return *reinterpret_cast<unsigned*>(&t);
}
__device__ __forceinline__ float ex2(float x){
    float r; asm("ex2.approx.f32 %0, %1;" : "=f"(r) : "f"(x)); return r;
}
__device__ __forceinline__ float tanhA(float x){
    float r; asm("tanh.approx.f32 %0, %1;" : "=f"(r) : "f"(x)); return r;
}

// ---------------- fp32 -> bf16 conversion of hidden states ----------------
__global__ void cvt_hs(const float* __restrict__ hs){
    int i = blockIdx.x * blockDim.x + threadIdx.x;
    const float4* p = (const float4*)hs;
    float4 v0 = p[2*i], v1 = p[2*i+1];
    unsigned u[4] = { packbf(v0.x,v0.y), packbf(v0.z,v0.w),
                      packbf(v1.x,v1.y), packbf(v1.z,v1.w) };
    *(uint4*)&g_hsb[(size_t)8*i] = *(uint4*)u;
}

// ---------------- weight transpose to bf16 ----------------
__global__ void transpose_w(const float* __restrict__ W0, const float* __restrict__ W1,
                            const float* __restrict__ W2, const float* __restrict__ W3)
{
    __shared__ float t[32][33];
    int mat = blockIdx.z;
    const float* W = (mat==0)?W0:(mat==1)?W1:(mat==2)?W2:W3;
    __nv_bfloat16* WT = g_WT + (size_t)mat*Hc*Hc;
    int kb = blockIdx.x*32, nb = blockIdx.y*32;
    int tx = threadIdx.x, ty = threadIdx.y;
    #pragma unroll
    for (int i = 0; i < 32; i += 8)
        t[ty+i][tx] = W[(size_t)(kb+ty+i)*Hc + nb+tx];
    __syncthreads();
    #pragma unroll
    for (int i = 0; i < 32; i += 8)
        WT[(size_t)(nb+ty+i)*Hc + kb+tx] = __float2bfloat16(t[tx][ty+i]);
}

// ---------------- mask MLPs ----------------
__global__ void mask_mlp_kernel(const float* __restrict__ imp,
    const float* __restrict__ rw1, const float* __restrict__ rb1,
    const float* __restrict__ rw2, const float* __restrict__ rb2,
    const float* __restrict__ aw1, const float* __restrict__ ab1,
    const float* __restrict__ aw2, const float* __restrict__ ab2)
{
    int idx = blockIdx.x * blockDim.x + threadIdx.x;
    if (idx >= Bc*Sc) return;
    float x = imp[idx];
    float hr[MLPc], ha[MLPc];
    const float kInvSqrt2 = 0.70710678118654752440f;
    #pragma unroll
    for (int j = 0; j < MLPc; j++) {
        float t = fmaf(x, rw1[j], rb1[j]);
        hr[j] = 0.5f * t * (1.0f + erff(t * kInvSqrt2));
        float u = fmaf(x, aw1[j], ab1[j]);
        ha[j] = 0.5f * u * (1.0f + erff(u * kInvSqrt2));
    }
    int b = idx / Sc, s = idx - b * Sc;
    #pragma unroll
    for (int h = 0; h < NHc; h++) {
        float rs = rb2[h], as = ab2[h];
        #pragma unroll
        for (int j = 0; j < MLPc; j++) {
            rs = fmaf(hr[j], rw2[j*NHc + h], rs);
            as = fmaf(ha[j], aw2[j*NHc + h], as);
        }
        g_reach[(b*NHc + h)*Sc + s]   = rs;
        g_attract[(b*NHc + h)*Sc + s] = as;
    }
}

// ---------------- bf16 tensor-core GEMM: K-chunk 32, 4 stages ----------------
#define AST2 40
#define ASZ2 (128*AST2)
#define STG2 (2*ASZ2)
#define G_SMEMB (4*STG2*2)

template<int MODE>
__global__ __launch_bounds__(256, 2) void gemm_tc(
    const float* __restrict__ b0p, const float* __restrict__ b1p,
    const float* __restrict__ b2p)
{
    extern __shared__ __nv_bfloat16 smB[];
    uint32_t smb = smem_u32(smB);

    const __nv_bfloat16* A = (MODE == 1) ? g_attnb : g_hsb;
    int wsel = (MODE == 0) ? (blockIdx.x >> 3) : 3;
    const __nv_bfloat16* WT = g_WT + (size_t)wsel * Hc * Hc;
    const float* bias = (MODE == 1) ? b0p : ((wsel == 0) ? b0p : (wsel == 1) ? b1p : b2p);
    int n0 = (MODE == 0) ? ((blockIdx.x & 7) * 128) : (blockIdx.x * 128);
    int m0 = blockIdx.y * 128;

    int tid = threadIdx.x;
    int wid = tid >> 5, lane = tid & 31;
    int mw = wid & 3, nw = wid >> 2;
    int g = lane >> 2, tq = lane & 3;

    int crow = tid >> 2, ccol = (tid & 3) * 8;

    float C[2][8][4];
    #pragma unroll
    for (int mt = 0; mt < 2; mt++)
        #pragma unroll
        for (int nt = 0; nt < 8; nt++)
            #pragma unroll
            for (int q = 0; q < 4; q++) C[mt][nt][q] = 0.f;

    #pragma unroll
    for (int s = 0; s < 3; s++) {
        int k0 = s * 32;
        uint32_t base = smb + (uint32_t)(s * STG2) * 2u;
        cpa16(base + (crow*AST2 + ccol)*2,        &A[(size_t)(m0 + crow)*Hc + k0 + ccol]);
        cpa16(base + ((crow+64)*AST2 + ccol)*2,   &A[(size_t)(m0 + crow + 64)*Hc + k0 + ccol]);
        cpa16(base + (ASZ2 + crow*AST2 + ccol)*2, &WT[(size_t)(n0 + crow)*Hc + k0 + ccol]);
        cpa16(base + (ASZ2 + (crow+64)*AST2 + ccol)*2, &WT[(size_t)(n0 + crow + 64)*Hc + k0 + ccol]);
        CP_COMMIT();
    }

    int l15 = lane & 15;
    int lc8 = (lane & 16) >> 1;
    uint32_t a_ld = smb + (uint32_t)(((mw*32 + l15)*AST2 + lc8) * 2);
    uint32_t b_ld = smb + (uint32_t)ASZ2*2u + (uint32_t)(((nw*64 + l15)*AST2 + lc8) * 2);

    for (int kt = 0; kt < 32; kt++) {
        CP_WAIT(2);
        __syncthreads();
        if (kt + 3 < 32) {
            int k0 = (kt + 3) * 32;
            uint32_t base = smb + (uint32_t)(((kt + 3) & 3) * STG2) * 2u;
            cpa16(base + (crow*AST2 + ccol)*2,        &A[(size_t)(m0 + crow)*Hc + k0 + ccol]);
            cpa16(base + ((crow+64)*AST2 + ccol)*2,   &A[(size_t)(m0 + crow + 64)*Hc + k0 + ccol]);
            cpa16(base + (ASZ2 + crow*AST2 + ccol)*2, &WT[(size_t)(n0 + crow)*Hc + k0 + ccol]);
            cpa16(base + (ASZ2 + (crow+64)*AST2 + ccol)*2, &WT[(size_t)(n0 + crow + 64)*Hc + k0 + ccol]);
        }
        CP_COMMIT();

        uint32_t so = (uint32_t)((kt & 3) * STG2) * 2u;
        #pragma unroll
        for (int ks = 0; ks < 2; ks++) {
            unsigned a0f[4], a1f[4];
            ldsm4(a0f, a_ld + so + ks*32);
            ldsm4(a1f, a_ld + so + (uint32_t)(16*AST2)*2u + ks*32);
            #pragma unroll
            for (int ntp = 0; ntp < 4; ntp++) {
                unsigned bb[4];
                ldsm4(bb, b_ld + so + (uint32_t)(ntp*16*AST2)*2u + ks*32);
                mma16(C[0][2*ntp],   a0f[0],a0f[1],a0f[2],a0f[3], bb[0], bb[2]);
                mma16(C[1][2*ntp],   a1f[0],a1f[1],a1f[2],a1f[3], bb[0], bb[2]);
                mma16(C[0][2*ntp+1], a0f[0],a0f[1],a0f[2],a0f[3], bb[1], bb[3]);
                mma16(C[1][2*ntp+1], a1f[0],a1f[1],a1f[2],a1f[3], bb[1], bb[3]);
            }
        }
    }

    #pragma unroll
    for (int mt = 0; mt < 2; mt++) {
        int r0 = m0 + mw*32 + mt*16 + g;
        #pragma unroll
        for (int nt = 0; nt < 8; nt++) {
            int col = n0 + nw*64 + nt*8 + 2*tq;
            float2 bv = *(const float2*)&bias[col];
            float c00 = C[mt][nt][0] + bv.x, c01 = C[mt][nt][1] + bv.y;
            float c10 = C[mt][nt][2] + bv.x, c11 = C[mt][nt][3] + bv.y;
            if (MODE == 0) {
                int hh = col >> 6, dd = col & 63;
                int bb2 = r0 >> 11, ss0 = r0 & 2047;
                __nv_bfloat16* outp = (wsel == 0) ? g_Qb : (wsel == 1) ? g_Kb : g_Vb;
                size_t i0 = (((size_t)bb2*NHc + hh)*Sc + ss0)*HDc + dd;
                *(unsigned*)&outp[i0]          = packbf(c00, c01);
                *(unsigned*)&outp[i0 + 8*HDc]  = packbf(c10, c11);
            } else {
                *(float2*)&g_proj[(size_t)r0*Hc + col]     = make_float2(c00, c01);
                *(float2*)&g_proj[(size_t)(r0+8)*Hc + col] = make_float2(c10, c11);
            }
        }
    }
}

// ---------------- bf16 flash attention: 128q x 64k, 3-stage, tanh sigmoid ----
// V stored (B,NH,S,HD); PV B-fragments via ldmatrix.trans.
#define FSTB 72
#define FQ_BYTES (128*FSTB*2)
#define FK_BYTES (64*FSTB*2)
#define FSTG_BYTES (2*FK_BYTES + 256)
#define FL_SMEMB (FQ_BYTES + 3*FSTG_BYTES)

__global__ __launch_bounds__(128, 2) void flash_tc(const float* __restrict__ log_temp)
{
    extern __shared__ char smc[];
    uint32_t smb = smem_u32(smc);
    int tid = threadIdx.x, wid = tid >> 5, lane = tid & 31;
    int g = lane >> 2, tq = lane & 3;
    int bh = blockIdx.y, b = bh >> 4, h = bh & 15;
    int q0 = blockIdx.x * 128;

    const __nv_bfloat16* Qg = g_Qb + ((size_t)bh*Sc + q0) * HDc;
    const __nv_bfloat16* Kg = g_Kb + (size_t)bh*Sc*HDc;
    const __nv_bfloat16* Vg = g_Vb + (size_t)bh*Sc*HDc;
    const float* att = g_attract + bh*Sc;

    #pragma unroll
    for (int l = 0; l < 8; l++) {
        int idx = tid + 128*l; int r = idx >> 3, c = (idx & 7) * 8;
        cpa16(smb + (uint32_t)((r*FSTB + c)*2), &Qg[r*HDc + c]);
    }
    #pragma unroll
    for (int s = 0; s < 2; s++) {
        uint32_t base = smb + (uint32_t)(FQ_BYTES + s*FSTG_BYTES);
        int kn = s * 64;
        #pragma unroll
        for (int l = 0; l < 4; l++) {
            int idx = tid + 128*l; int r = idx >> 3, c = (idx & 7) * 8;
            cpa16(base + (uint32_t)((r*FSTB + c)*2), &Kg[(size_t)(kn + r)*HDc + c]);
            cpa16(base + (uint32_t)FK_BYTES + (uint32_t)((r*FSTB + c)*2), &Vg[(size_t)(kn + r)*HDc + c]);
        }
        if (tid < 16) cpa16(base + (uint32_t)(2*FK_BYTES) + tid*16, &att[kn + tid*4]);
        CP_COMMIT();
    }

    int l15 = lane & 15;
    int lc8 = (lane & 16) >> 1;
    uint32_t qa   = smb + (uint32_t)(((wid*32 + l15)*FSTB + lc8) * 2);
    uint32_t kvof = (uint32_t)((l15*FSTB + lc8) * 2);
    uint32_t vof = (uint32_t)((((lane & 7) + ((lane & 16) >> 1))*FSTB + (lane & 8)) * 2);

    const float L2E = 1.44269504088896f;
    const float SCL = 0.125f * L2E;

    float reach05[2][2], ip[2][2];
    #pragma unroll
    for (int mt = 0; mt < 2; mt++) {
        int rr = q0 + wid*32 + mt*16 + g;
        reach05[mt][0] = 0.5f * g_reach[bh*Sc + rr];
        reach05[mt][1] = 0.5f * g_reach[bh*Sc + rr + 8];
        ip[mt][0] = (float)rr; ip[mt][1] = (float)(rr + 8);
    }
    float temp  = __expf(log_temp[h]) + 1.0f;
    float inv05 = __fdividef(0.5f, (float)Sc * temp);
    const float HALF8 = 0.5f + 1e-8f;

    float mrow[2][2], lrow[2][2];
    float O[2][8][4];
    #pragma unroll
    for (int mt = 0; mt < 2; mt++) {
        mrow[mt][0] = mrow[mt][1] = -1e30f;
        lrow[mt][0] = lrow[mt][1] = 0.f;
        #pragma unroll
        for (int nt = 0; nt < 8; nt++)
            #pragma unroll
            for (int q = 0; q < 4; q++) O[mt][nt][q] = 0.f;
    }

    for (int kt = 0; kt < 32; kt++) {
        int k0 = kt * 64;
        CP_WAIT(1);
        __syncthreads();
        if (kt + 2 < 32) {
            int kn = (kt + 2) * 64;
            uint32_t base = smb + (uint32_t)(FQ_BYTES + ((kt + 2) % 3) * FSTG_BYTES);
            #pragma unroll
            for (int l = 0; l < 4; l++) {
                int idx = tid + 128*l; int r = idx >> 3, c = (idx & 7) * 8;
                cpa16(base + (uint32_t)((r*FSTB + c)*2), &Kg[(size_t)(kn + r)*HDc + c]);
                cpa16(base + (uint32_t)FK_BYTES + (uint32_t)((r*FSTB + c)*2), &Vg[(size_t)(kn + r)*HDc + c]);
            }
            if (tid < 16) cpa16(base + (uint32_t)(2*FK_BYTES) + tid*16, &att[kn + tid*4]);
        }
        CP_COMMIT();

        int st = kt % 3;
        uint32_t stg = smb + (uint32_t)(FQ_BYTES + st * FSTG_BYTES);
        uint32_t Kb = stg + kvof;
        uint32_t Vb = stg + (uint32_t)FK_BYTES + vof;
        const float* Att = (const float*)(smc + FQ_BYTES + st * FSTG_BYTES + 2*FK_BYTES);

        // ---- S = Q K^T ----
        float C[2][8][4];
        #pragma unroll
        for (int mt = 0; mt < 2; mt++)
            #pragma unroll
            for (int nt = 0; nt < 8; nt++)
                #pragma unroll
                for (int q = 0; q < 4; q++) C[mt][nt][q] = 0.f;
        #pragma unroll
        for (int ks = 0; ks < 4; ks++) {
            unsigned a0f[4], a1f[4];
            ldsm4(a0f, qa + ks*32);
            ldsm4(a1f, qa + (uint32_t)(16*FSTB)*2u + ks*32);
            #pragma unroll
            for (int ntp = 0; ntp < 4; ntp++) {
                unsigned bb[4];
                ldsm4(bb, Kb + (uint32_t)(ntp*16*FSTB)*2u + ks*32);
                mma16(C[0][2*ntp],   a0f[0],a0f[1],a0f[2],a0f[3], bb[0], bb[2]);
                mma16(C[1][2*ntp],   a1f[0],a1f[1],a1f[2],a1f[3], bb[0], bb[2]);
                mma16(C[0][2*ntp+1], a0f[0],a0f[1],a0f[2],a0f[3], bb[1], bb[3]);
                mma16(C[1][2*ntp+1], a1f[0],a1f[1],a1f[2],a1f[3], bb[1], bb[3]);
            }
        }

        // ---- max pass + corr ----
        float mn[2][2], corr[2][2], mns[2][2];
        #pragma unroll
        for (int mt = 0; mt < 2; mt++) {
            float ml = -1e30f, mh = -1e30f;
            #pragma unroll
            for (int nt = 0; nt < 8; nt++) {
                ml = fmaxf(ml, fmaxf(C[mt][nt][0], C[mt][nt][1]));
                mh = fmaxf(mh, fmaxf(C[mt][nt][2], C[mt][nt][3]));
            }
            ml = fmaxf(ml, __shfl_xor_sync(0xffffffffu, ml, 1));
            ml = fmaxf(ml, __shfl_xor_sync(0xffffffffu, ml, 2));
            mh = fmaxf(mh, __shfl_xor_sync(0xffffffffu, mh, 1));
            mh = fmaxf(mh, __shfl_xor_sync(0xffffffffu, mh, 2));
            mn[mt][0] = fmaxf(mrow[mt][0], ml);
            mn[mt][1] = fmaxf(mrow[mt][1], mh);
            corr[mt][0] = ex2((mrow[mt][0] - mn[mt][0]) * SCL);
            corr[mt][1] = ex2((mrow[mt][1] - mn[mt][1]) * SCL);
            mrow[mt][0] = mn[mt][0]; mrow[mt][1] = mn[mt][1];
            mns[mt][0] = mn[mt][0] * SCL; mns[mt][1] = mn[mt][1] * SCL;
        }

        bool need = (corr[0][0] != 1.f) | (corr[0][1] != 1.f) |
                    (corr[1][0] != 1.f) | (corr[1][1] != 1.f);
        if (__any_sync(0xffffffffu, need)) {
            #pragma unroll
            for (int mt = 0; mt < 2; mt++)
                #pragma unroll
                for (int nt = 0; nt < 8; nt++) {
                    O[mt][nt][0] *= corr[mt][0]; O[mt][nt][1] *= corr[mt][0];
                    O[mt][nt][2] *= corr[mt][1]; O[mt][nt][3] *= corr[mt][1];
                }
        }

        // ---- P = (0.5*tanh(z/2) + 0.5 + 1e-8) * exp2(SCL*C - mns) ----
        #pragma unroll
        for (int mt = 0; mt < 2; mt++) {
            float rs0 = 0.f, rs1 = 0.f;
            #pragma unroll
            for (int nt = 0; nt < 8; nt++) {
                int jc = nt*8 + 2*tq;
                float2 at2 = *(const float2*)&Att[jc];
                float j0 = (float)(k0 + jc), j1 = j0 + 1.0f;
                float a0b = fmaf(at2.x, 0.5f, reach05[mt][0]);
                float a1b = fmaf(at2.y, 0.5f, reach05[mt][0]);
                float b0b = fmaf(at2.x, 0.5f, reach05[mt][1]);
                float b1b = fmaf(at2.y, 0.5f, reach05[mt][1]);
                float zh00 = fmaf(-inv05, fabsf(ip[mt][0] - j0), a0b);
                float zh01 = fmaf(-inv05, fabsf(ip[mt][0] - j1), a1b);
                float zh10 = fmaf(-inv05, fabsf(ip[mt][1] - j0), b0b);
                float zh11 = fmaf(-inv05, fabsf(ip[mt][1] - j1), b1b);
                float w00 = fmaf(tanhA(zh00), 0.5f, HALF8);
                float w01 = fmaf(tanhA(zh01), 0.5f, HALF8);
                float w10 = fmaf(tanhA(zh10), 0.5f, HALF8);
                float w11 = fmaf(tanhA(zh11), 0.5f, HALF8);
                C[mt][nt][0] = w00 * ex2(fmaf(C[mt][nt][0], SCL, -mns[mt][0]));
                C[mt][nt][1] = w01 * ex2(fmaf(C[mt][nt][1], SCL, -mns[mt][0]));
                C[mt][nt][2] = w10 * ex2(fmaf(C[mt][nt][2], SCL, -mns[mt][1]));
                C[mt][nt][3] = w11 * ex2(fmaf(C[mt][nt][3], SCL, -mns[mt][1]));
                rs0 += C[mt][nt][0] + C[mt][nt][1];
                rs1 += C[mt][nt][2] + C[mt][nt][3];
            }
            rs0 += __shfl_xor_sync(0xffffffffu, rs0, 1);
            rs0 += __shfl_xor_sync(0xffffffffu, rs0, 2);
            rs1 += __shfl_xor_sync(0xffffffffu, rs1, 1);
            rs1 += __shfl_xor_sync(0xffffffffu, rs1, 2);
            lrow[mt][0] = fmaf(lrow[mt][0], corr[mt][0], rs0);
            lrow[mt][1] = fmaf(lrow[mt][1], corr[mt][1], rs1);
        }

        // ---- O += P V : trans-ldmatrix V fragments ----
        #pragma unroll
        for (int ks = 0; ks < 4; ks++) {
            unsigned af0[4], af1[4];
            af0[0] = packbf(C[0][2*ks][0],   C[0][2*ks][1]);
            af0[1] = packbf(C[0][2*ks][2],   C[0][2*ks][3]);
            af0[2] = packbf(C[0][2*ks+1][0], C[0][2*ks+1][1]);
            af0[3] = packbf(C[0][2*ks+1][2], C[0][2*ks+1][3]);
            af1[0] = packbf(C[1][2*ks][0],   C[1][2*ks][1]);
            af1[1] = packbf(C[1][2*ks][2],   C[1][2*ks][3]);
            af1[2] = packbf(C[1][2*ks+1][0], C[1][2*ks+1][1]);
            af1[3] = packbf(C[1][2*ks+1][2], C[1][2*ks+1][3]);
            #pragma unroll
            for (int ntp = 0; ntp < 4; ntp++) {
                unsigned bb[4];
                ldsm4t(bb, Vb + (uint32_t)(ks*16*FSTB)*2u + (uint32_t)(ntp*32));
                mma16(O[0][2*ntp],   af0[0],af0[1],af0[2],af0[3], bb[0], bb[2]);
                mma16(O[1][2*ntp],   af1[0],af1[1],af1[2],af1[3], bb[0], bb[2]);
                mma16(O[0][2*ntp+1], af0[0],af0[1],af0[2],af0[3], bb[1], bb[3]);
                mma16(O[1][2*ntp+1], af1[0],af1[1],af1[2],af1[3], bb[1], bb[3]);
            }
        }
    }

    #pragma unroll
    for (int mt = 0; mt < 2; mt++) {
        float il0 = __fdividef(1.f, lrow[mt][0]);
        float il1 = __fdividef(1.f, lrow[mt][1]);
        int rr = q0 + wid*32 + mt*16 + g;
        #pragma unroll
        for (int nt = 0; nt < 8; nt++) {
            int col = h*HDc + nt*8 + 2*tq;
            *(unsigned*)&g_attnb[(size_t)(b*Sc + rr    )*Hc + col] =
                packbf(O[mt][nt][0]*il0, O[mt][nt][1]*il0);
            *(unsigned*)&g_attnb[(size_t)(b*Sc + rr + 8)*Hc + col] =
                packbf(O[mt][nt][2]*il1, O[mt][nt][3]*il1);
        }
    }
}

// ---------------- residual + LayerNorm ----------------
__global__ __launch_bounds__(256) void ln_kernel(
    const float* __restrict__ hs, const float* __restrict__ gamma,
    const float* __restrict__ beta, float* __restrict__ out)
{
    int m = blockIdx.x;
    __shared__ float xs[Hc];
    __shared__ float red[8];
    __shared__ float stat[2];
    int tid = threadIdx.x;
    const float* hrow = hs + (size_t)m*Hc;
    const float* prow = g_proj + (size_t)m*Hc;

    float lsum = 0.f;
    for (int i = tid; i < Hc; i += 256) {
        float x = hrow[i] + prow[i];
        xs[i] = x;
        lsum += x;
    }
    #pragma unroll
    for (int o = 16; o > 0; o >>= 1) lsum += __shfl_xor_sync(0xffffffffu, lsum, o);
    if ((tid & 31) == 0) red[tid >> 5] = lsum;
    __syncthreads();
    if (tid == 0) {
        float s = 0.f;
        #pragma unroll
        for (int i = 0; i < 8; i++) s += red[i];
        stat[0] = s * (1.0f/(float)Hc);
    }
    __syncthreads();
    float mu = stat[0];

    float lvar = 0.f;
    for (int i = tid; i < Hc; i += 256) {
        float d = xs[i] - mu;
        lvar += d*d;
    }
    #pragma unroll
    for (int o = 16; o > 0; o >>= 1) lvar += __shfl_xor_sync(0xffffffffu, lvar, o);
    if ((tid & 31) == 0) red[tid >> 5] = lvar;
    __syncthreads();
    if (tid == 0) {
        float s = 0.f;
        #pragma unroll
        for (int i = 0; i < 8; i++) s += red[i];
        stat[1] = rsqrtf(s * (1.0f/(float)Hc) + 1e-5f);
    }
    __syncthreads();
    float rstd = stat[1];

    float* orow = out + (size_t)m*Hc;
    for (int i = tid; i < Hc; i += 256)
        orow[i] = (xs[i] - mu) * rstd * gamma[i] + beta[i];
}

// ---------------- launch ----------------
extern "C" void kernel_launch(void* const* d_in, const int* in_sizes, int n_in,
                              void* d_out, int out_size) {
    (void)in_sizes; (void)n_in; (void)out_size;
    const float* hs   = (const float*)d_in[0];
    const float* imp  = (const float*)d_in[1];
    const float* wq   = (const float*)d_in[2];
    const float* bq   = (const float*)d_in[3];
    const float* wk   = (const float*)d_in[4];
    const float* bk   = (const float*)d_in[5];
    const float* wv   = (const float*)d_in[6];
    const float* bv   = (const float*)d_in[7];
    const float* wo   = (const float*)d_in[8];
    const float* bo   = (const float*)d_in[9];
    const float* rw1  = (const float*)d_in[10];
    const float* rb1  = (const float*)d_in[11];
    const float* rw2  = (const float*)d_in[12];
    const float* rb2  = (const float*)d_in[13];
    const float* aw1  = (const float*)d_in[14];
    const float* ab1  = (const float*)d_in[15];
    const float* aw2  = (const float*)d_in[16];
    const float* ab2  = (const float*)d_in[17];
    const float* logt = (const float*)d_in[18];
    const float* lng  = (const float*)d_in[19];
    const float* lnb  = (const float*)d_in[20];
    float* out = (float*)d_out;

    cudaFuncSetAttribute(gemm_tc<0>, cudaFuncAttributeMaxDynamicSharedMemorySize, G_SMEMB);
    cudaFuncSetAttribute(gemm_tc<1>, cudaFuncAttributeMaxDynamicSharedMemorySize, G_SMEMB);
    cudaFuncSetAttribute(flash_tc,   cudaFuncAttributeMaxDynamicSharedMemorySize, FL_SMEMB);

    cvt_hs<<<Mtot*Hc/8/256, 256>>>(hs);
    transpose_w<<<dim3(32, 32, 4), dim3(32, 8)>>>(wq, wk, wv, wo);
    mask_mlp_kernel<<<(Bc*Sc + 255)/256, 256>>>(imp, rw1, rb1, rw2, rb2,
                                                aw1, ab1, aw2, ab2);

    gemm_tc<0><<<dim3(24, Mtot/128), 256, G_SMEMB>>>(bq, bk, bv);

    flash_tc<<<dim3(Sc/128, Bc*NHc), 128, FL_SMEMB>>>(logt);

    gemm_tc<1><<<dim3(8, Mtot/128), 256, G_SMEMB>>>(bo, bo, bo);

    ln_kernel<<<Mtot, 256>>>(hs, lng, lnb, out);
}